// round 2
// baseline (speedup 1.0000x reference)
#include <cuda_runtime.h>
#include <cstdint>

// ---------------- problem constants ----------------
#define BATCH     32
#define LEN       220500
#define NFFT      2048
#define HOP       512
#define PADW      1024
#define FREQ      1025
#define NFRAMES   431
#define NBT       (BATCH * NFRAMES)     // 13792
#define XPLEN     (LEN + 2 * PADW)      // 222548
#define XPSTRIDE  222560                // padded to mult of 32
#define KDIM      1024                  // folded K
#define NPAD      13824                 // 216 * 64, GEMM N stride
#define MPAD      1088                  // 17 * 64, GEMM M stride

// ---------------- device scratch (zero-initialized by CUDA) ----------------
__device__ float g_xp [BATCH * XPSTRIDE];     // padded input  (~28.5 MB)
__device__ float g_Ut [KDIM * NPAD];          // even-fold frames, transposed (~56.6 MB)
__device__ float g_Vt [KDIM * NPAD];          // odd-fold frames, transposed  (~56.6 MB)
__device__ float g_Wct[KDIM * MPAD];          // wcos[k][j+1] transposed (~4.5 MB)
__device__ float g_Wst[KDIM * MPAD];          // wsin[k][j+1] transposed

// ---------------- kernel 1: reflect pad ----------------
__global__ void pad_kernel(const float* __restrict__ x) {
    int i = blockIdx.x * blockDim.x + threadIdx.x;
    int b = blockIdx.y;
    if (i >= XPLEN) return;
    int m = i - PADW;
    if (m < 0) m = -m;
    else if (m >= LEN) m = 2 * LEN - 2 - m;
    g_xp[b * XPSTRIDE + i] = x[(size_t)b * LEN + m];
}

// ---------------- kernel 2: transpose + shift weights ----------------
// g_Wct[j][k] = wcos[k][j+1], k < 1025 (pad cols zeroed)
__global__ void wprep_kernel(const float* __restrict__ wcos,
                             const float* __restrict__ wsin) {
    int k = blockIdx.x * blockDim.x + threadIdx.x;   // 0..MPAD-1
    int j = blockIdx.y;                              // 0..KDIM-1
    if (k >= MPAD) return;
    float c = 0.f, s = 0.f;
    if (k < FREQ) {
        c = wcos[(size_t)k * NFFT + j + 1];
        s = wsin[(size_t)k * NFFT + j + 1];
    }
    g_Wct[j * MPAD + k] = c;
    g_Wst[j * MPAD + k] = s;
}

// ---------------- kernel 3: build folded frame matrices (transposed) ----------------
// U[j][bt] = f[j+1] + f[2047-j]   (j==1023 -> f[1024], center tap once)
// V[j][bt] = f[j+1] - f[2047-j]
__global__ void __launch_bounds__(256) frame_kernel() {
    int btl = threadIdx.x & 63;
    int jl  = threadIdx.x >> 6;          // 0..3
    int bt = blockIdx.x * 64 + btl;
    if (bt >= NBT) return;               // pad columns stay zero
    int b = bt / NFRAMES;
    int t = bt - b * NFRAMES;
    const float* __restrict__ xf = g_xp + b * XPSTRIDE + t * HOP;
    int jbase = blockIdx.y * 128 + jl * 32;
#pragma unroll 4
    for (int it = 0; it < 32; ++it) {
        int j = jbase + it;
        float a  = xf[j + 1];
        float bb = xf[2047 - j];
        float u = a + bb;
        float v = a - bb;
        if (j == 1023) { u = xf[1024]; v = 0.f; }
        g_Ut[(size_t)j * NPAD + bt] = u;
        g_Vt[(size_t)j * NPAD + bt] = v;
    }
}

// ---------------- kernel 4: tiled SGEMM, 64x64 tile, 4x4 microtile ----------------
// z=0: real = Wct^T(U-columns) ; z=1: imag = -(Wst · V)
__global__ void __launch_bounds__(256) gemm_kernel(float* __restrict__ out) {
    const int z = blockIdx.z;
    const float* __restrict__ W = z ? g_Wst : g_Wct;
    const float* __restrict__ X = z ? g_Vt  : g_Ut;

    __shared__ float Ws[16][64];
    __shared__ float Xs[16][64];

    const int tid = threadIdx.x;
    const int tx = tid & 15;          // column group (frames)
    const int ty = tid >> 4;          // row group (bins)
    const int k0 = blockIdx.y * 64;   // bin tile base    (17 tiles -> 1088 = MPAD)
    const int n0 = blockIdx.x * 64;   // frame tile base  (216 tiles -> 13824 = NPAD)

    // staging-load assignment: one float4 per thread per tile
    const int lj = tid >> 4;          // 0..15 : j within chunk
    const int lk = (tid & 15) * 4;    // 0..60 : col within tile
    const float* Wp = W + (size_t)lj * MPAD + k0 + lk;
    const float* Xp = X + (size_t)lj * NPAD + n0 + lk;

    float4 wreg = *(const float4*)Wp;
    float4 xreg = *(const float4*)Xp;

    float acc[4][4];
#pragma unroll
    for (int i = 0; i < 4; ++i)
#pragma unroll
        for (int l = 0; l < 4; ++l) acc[i][l] = 0.f;

    for (int c = 0; c < KDIM / 16; ++c) {
        *(float4*)&Ws[lj][lk] = wreg;
        *(float4*)&Xs[lj][lk] = xreg;
        __syncthreads();
        if (c < KDIM / 16 - 1) {      // prefetch next chunk (hides gmem latency)
            wreg = *(const float4*)(Wp + (size_t)(c + 1) * 16 * MPAD);
            xreg = *(const float4*)(Xp + (size_t)(c + 1) * 16 * NPAD);
        }
#pragma unroll
        for (int j = 0; j < 16; ++j) {
            float4 wv = *(const float4*)&Ws[j][ty * 4];
            float4 xv = *(const float4*)&Xs[j][tx * 4];
            acc[0][0] += wv.x * xv.x; acc[0][1] += wv.x * xv.y;
            acc[0][2] += wv.x * xv.z; acc[0][3] += wv.x * xv.w;
            acc[1][0] += wv.y * xv.x; acc[1][1] += wv.y * xv.y;
            acc[1][2] += wv.y * xv.z; acc[1][3] += wv.y * xv.w;
            acc[2][0] += wv.z * xv.x; acc[2][1] += wv.z * xv.y;
            acc[2][2] += wv.z * xv.z; acc[2][3] += wv.z * xv.w;
            acc[3][0] += wv.w * xv.x; acc[3][1] += wv.w * xv.y;
            acc[3][2] += wv.w * xv.z; acc[3][3] += wv.w * xv.w;
        }
        __syncthreads();
    }

    // epilogue: out[b][k][t][z], imag negated
#pragma unroll
    for (int i = 0; i < 4; ++i) {
        int k = k0 + ty * 4 + i;
        if (k >= FREQ) continue;
#pragma unroll
        for (int l = 0; l < 4; ++l) {
            int bt = n0 + tx * 4 + l;
            if (bt >= NBT) continue;
            int b = bt / NFRAMES;
            int t = bt - b * NFRAMES;
            float v = z ? -acc[i][l] : acc[i][l];
            out[((((size_t)b * FREQ + k) * NFRAMES + t) << 1) + z] = v;
        }
    }
}

// ---------------- launch ----------------
extern "C" void kernel_launch(void* const* d_in, const int* in_sizes, int n_in,
                              void* d_out, int out_size) {
    const float* x    = (const float*)d_in[0];
    const float* wcos = (const float*)d_in[1];
    const float* wsin = (const float*)d_in[2];
    float* out = (float*)d_out;

    pad_kernel<<<dim3((XPLEN + 255) / 256, BATCH), 256>>>(x);
    wprep_kernel<<<dim3((MPAD + 127) / 128, KDIM), 128>>>(wcos, wsin);
    frame_kernel<<<dim3((NBT + 63) / 64, 8), 256>>>();
    gemm_kernel<<<dim3(NPAD / 64, MPAD / 64, 2), 256>>>(out);
}

// round 3
// speedup vs baseline: 2.5753x; 2.5753x over previous
#include <cuda_runtime.h>
#include <cstdint>

// ---------------- problem constants ----------------
#define BATCH     32
#define LEN       220500
#define NFFT      2048
#define HOP       512
#define PADW      1024
#define FREQ      1025
#define NFRAMES   431
#define NBT       (BATCH * NFRAMES)     // 13792
#define XPLEN     (LEN + 2 * PADW)      // 222548
#define XPSTRIDE  222560
#define KDIM      1024                  // folded K
#define NPAD      13824                 // 108 * 128
#define MPAD      1152                  // 9 * 128
#define SSTR      136                   // smem row stride (floats) -> conflict-free frags

// ---------------- device scratch ----------------
__device__ float g_xp [BATCH * XPSTRIDE];
__device__ float g_Ut [KDIM * NPAD];
__device__ float g_Vt [KDIM * NPAD];
__device__ float g_Wct[KDIM * MPAD];
__device__ float g_Wst[KDIM * MPAD];

__device__ __forceinline__ float tf32r(float x) {
    uint32_t u; asm("cvt.rna.tf32.f32 %0, %1;" : "=r"(u) : "f"(x));
    return __uint_as_float(u);
}

// ---------------- kernel 1: reflect pad ----------------
__global__ void pad_kernel(const float* __restrict__ x) {
    int i = blockIdx.x * blockDim.x + threadIdx.x;
    int b = blockIdx.y;
    if (i >= XPLEN) return;
    int m = i - PADW;
    if (m < 0) m = -m;
    else if (m >= LEN) m = 2 * LEN - 2 - m;
    g_xp[b * XPSTRIDE + i] = x[(size_t)b * LEN + m];
}

// ---------------- kernel 2: transpose + shift weights (tf32-rounded) ----------------
__global__ void wprep_kernel(const float* __restrict__ wcos,
                             const float* __restrict__ wsin) {
    int k = blockIdx.x * blockDim.x + threadIdx.x;
    int j = blockIdx.y;
    if (k >= MPAD) return;
    float c = 0.f, s = 0.f;
    if (k < FREQ) {
        c = tf32r(wcos[(size_t)k * NFFT + j + 1]);
        s = tf32r(wsin[(size_t)k * NFFT + j + 1]);
    }
    g_Wct[j * MPAD + k] = c;
    g_Wst[j * MPAD + k] = s;
}

// ---------------- kernel 3: folded frame matrices (tf32-rounded) ----------------
__global__ void __launch_bounds__(256) frame_kernel() {
    int btl = threadIdx.x & 63;
    int jl  = threadIdx.x >> 6;
    int bt = blockIdx.x * 64 + btl;
    if (bt >= NBT) return;
    int b = bt / NFRAMES;
    int t = bt - b * NFRAMES;
    const float* __restrict__ xf = g_xp + b * XPSTRIDE + t * HOP;
    int jbase = blockIdx.y * 128 + jl * 32;
#pragma unroll 4
    for (int it = 0; it < 32; ++it) {
        int j = jbase + it;
        float a  = xf[j + 1];
        float bb = xf[2047 - j];
        float u = a + bb;
        float v = a - bb;
        if (j == 1023) { u = xf[1024]; v = 0.f; }
        g_Ut[(size_t)j * NPAD + bt] = tf32r(u);
        g_Vt[(size_t)j * NPAD + bt] = tf32r(v);
    }
}

// ---------------- kernel 4: TF32 mma.sync GEMM ----------------
// block tile 128(M) x 128(N), 8 warps (2x4), warp tile 64x32, k-step 16
#define MMA_TF32(d, a, b)                                                       \
    asm volatile(                                                               \
        "mma.sync.aligned.m16n8k8.row.col.f32.tf32.tf32.f32 "                   \
        "{%0,%1,%2,%3},{%4,%5,%6,%7},{%8,%9},{%0,%1,%2,%3};"                    \
        : "+f"(d[0]), "+f"(d[1]), "+f"(d[2]), "+f"(d[3])                        \
        : "r"(a[0]), "r"(a[1]), "r"(a[2]), "r"(a[3]), "r"(b[0]), "r"(b[1]))

__global__ void __launch_bounds__(256, 2) gemm_kernel(float* __restrict__ out) {
    const int z = blockIdx.z;
    const float* __restrict__ W = z ? g_Wst : g_Wct;
    const float* __restrict__ X = z ? g_Vt  : g_Ut;

    __shared__ float As[16 * SSTR];
    __shared__ float Bs[16 * SSTR];

    const int tid  = threadIdx.x;
    const int warp = tid >> 5, lane = tid & 31;
    const int wm = warp & 1;            // 0..1 : 64-row warp slab
    const int wn = warp >> 1;           // 0..3 : 32-col warp slab
    const int g  = lane >> 2;           // 0..7
    const int tg = lane & 3;            // 0..3
    const int m0 = blockIdx.y * 128;
    const int n0 = blockIdx.x * 128;

    // staging: each thread stores 2 float4 per tile (rows r and r+8)
    const int r  = tid >> 5;            // 0..7
    const int cc = lane * 4;            // 0..124
    const float* Ap = W + (size_t)r * MPAD + m0 + cc;
    const float* Bp = X + (size_t)r * NPAD + n0 + cc;

    float4 a0v = *(const float4*)Ap;
    float4 a1v = *(const float4*)(Ap + 8 * (size_t)MPAD);
    float4 b0v = *(const float4*)Bp;
    float4 b1v = *(const float4*)(Bp + 8 * (size_t)NPAD);

    float acc[4][4][4];
#pragma unroll
    for (int i = 0; i < 4; ++i)
#pragma unroll
        for (int j = 0; j < 4; ++j)
#pragma unroll
            for (int c = 0; c < 4; ++c) acc[i][j][c] = 0.f;

    const uint32_t* Asu = (const uint32_t*)As;
    const uint32_t* Bsu = (const uint32_t*)Bs;
    const int abase = wm * 64 + g;      // + tg row term added per substep
    const int bbase = wn * 32 + g;

    for (int c = 0; c < KDIM / 16; ++c) {
        *(float4*)&As[r * SSTR + cc]       = a0v;
        *(float4*)&As[(r + 8) * SSTR + cc] = a1v;
        *(float4*)&Bs[r * SSTR + cc]       = b0v;
        *(float4*)&Bs[(r + 8) * SSTR + cc] = b1v;
        __syncthreads();
        if (c + 1 < KDIM / 16) {
            const float* An = Ap + (size_t)(c + 1) * 16 * MPAD;
            const float* Bn = Bp + (size_t)(c + 1) * 16 * NPAD;
            a0v = *(const float4*)An;
            a1v = *(const float4*)(An + 8 * (size_t)MPAD);
            b0v = *(const float4*)Bn;
            b1v = *(const float4*)(Bn + 8 * (size_t)NPAD);
        }
#pragma unroll
        for (int s = 0; s < 2; ++s) {
            const int krow = 8 * s + tg;
            uint32_t bf[4][2];
#pragma unroll
            for (int j = 0; j < 4; ++j) {
                bf[j][0] = Bsu[krow * SSTR + bbase + 8 * j];
                bf[j][1] = Bsu[(krow + 4) * SSTR + bbase + 8 * j];
            }
#pragma unroll
            for (int i = 0; i < 4; ++i) {
                uint32_t af[4];
                const int mcol = abase + 16 * i;
                af[0] = Asu[krow * SSTR + mcol];
                af[1] = Asu[krow * SSTR + mcol + 8];
                af[2] = Asu[(krow + 4) * SSTR + mcol];
                af[3] = Asu[(krow + 4) * SSTR + mcol + 8];
#pragma unroll
                for (int j = 0; j < 4; ++j) MMA_TF32(acc[i][j], af, bf[j]);
            }
        }
        __syncthreads();
    }

    // epilogue: out[b][k][t][z], imag negated
    int btc[4][2], bc[4][2], tc[4][2];
#pragma unroll
    for (int j = 0; j < 4; ++j)
#pragma unroll
        for (int q = 0; q < 2; ++q) {
            int bt = n0 + wn * 32 + 8 * j + 2 * tg + q;
            btc[j][q] = bt;
            bc[j][q] = bt / NFRAMES;
            tc[j][q] = bt - bc[j][q] * NFRAMES;
        }
#pragma unroll
    for (int i = 0; i < 4; ++i) {
#pragma unroll
        for (int h = 0; h < 2; ++h) {
            int k = m0 + wm * 64 + 16 * i + g + 8 * h;
            if (k >= FREQ) continue;
#pragma unroll
            for (int j = 0; j < 4; ++j)
#pragma unroll
                for (int q = 0; q < 2; ++q) {
                    if (btc[j][q] >= NBT) continue;
                    float v = acc[i][j][2 * h + q];
                    if (z) v = -v;
                    out[((((size_t)bc[j][q] * FREQ + k) * NFRAMES + tc[j][q]) << 1) + z] = v;
                }
        }
    }
}

// ---------------- launch ----------------
extern "C" void kernel_launch(void* const* d_in, const int* in_sizes, int n_in,
                              void* d_out, int out_size) {
    const float* x    = (const float*)d_in[0];
    const float* wcos = (const float*)d_in[1];
    const float* wsin = (const float*)d_in[2];
    float* out = (float*)d_out;

    pad_kernel<<<dim3((XPLEN + 255) / 256, BATCH), 256>>>(x);
    wprep_kernel<<<dim3((MPAD + 127) / 128, KDIM), 128>>>(wcos, wsin);
    frame_kernel<<<dim3((NBT + 63) / 64, 8), 256>>>();
    gemm_kernel<<<dim3(NPAD / 128, MPAD / 128, 2), 256>>>(out);
}

// round 7
// speedup vs baseline: 3.3654x; 1.3068x over previous
#include <cuda_runtime.h>
#include <cstdint>

// ---------------- problem constants ----------------
#define BATCH     32
#define LEN       220500
#define HOP       512
#define PADW      1024
#define FREQ      1025
#define NFRAMES   431
#define NBT       (BATCH * NFRAMES)     // 13792
#define KDIM      1024                  // folded K
#define NPAD      13824                 // 108 * 128
#define MPAD      1152                  // 9 * 128
#define NFFT      2048
#define SSTR      136                   // smem row stride (floats) -> conflict-free frags
#define NKT       (KDIM / 16)           // 64 k-tiles

// ---------------- device scratch ----------------
__device__ float g_Ut [KDIM * NPAD];
__device__ float g_Vt [KDIM * NPAD];
__device__ float g_Wct[KDIM * MPAD];
__device__ float g_Wst[KDIM * MPAD];

__device__ __forceinline__ float tf32r(float x) {
    uint32_t u; asm("cvt.rna.tf32.f32 %0, %1;" : "=r"(u) : "f"(x));
    return __uint_as_float(u);
}

__device__ __forceinline__ void cpa16(uint32_t s, const void* g) {
    asm volatile("cp.async.cg.shared.global [%0], [%1], 16;" :: "r"(s), "l"(g));
}
__device__ __forceinline__ void cpa_commit() {
    asm volatile("cp.async.commit_group;" ::: "memory");
}
template <int N>
__device__ __forceinline__ void cpa_wait() {
    asm volatile("cp.async.wait_group %0;" :: "n"(N) : "memory");
}

// ---------------- kernel 1: transpose + shift weights (tf32-rounded) ----------------
__global__ void wprep_kernel(const float* __restrict__ wcos,
                             const float* __restrict__ wsin) {
    int k = blockIdx.x * blockDim.x + threadIdx.x;
    int j = blockIdx.y;
    if (k >= MPAD) return;
    float c = 0.f, s = 0.f;
    if (k < FREQ) {
        c = tf32r(wcos[(size_t)k * NFFT + j + 1]);
        s = tf32r(wsin[(size_t)k * NFFT + j + 1]);
    }
    g_Wct[j * MPAD + k] = c;
    g_Wst[j * MPAD + k] = s;
}

// ---------------- kernel 2: fused reflect-pad + fold + transpose ----------------
// base = t*HOP - PADW
// U[j][bt] = x[refl(base + j + 1)] + x[refl(base + 2047 - j)]   (j==1023 -> center tap once)
// V[j][bt] = x[refl(base + j + 1)] - x[refl(base + 2047 - j)]
__global__ void __launch_bounds__(256) frame_kernel(const float* __restrict__ x) {
    __shared__ float su[32][33];
    __shared__ float sv[32][33];
    const int b  = blockIdx.z;
    const int t0 = blockIdx.x * 32;
    const int j0 = blockIdx.y * 32;
    const int tx = threadIdx.x & 31;
    const int ty = threadIdx.x >> 5;
    const float* __restrict__ xb = x + (size_t)b * LEN;

#pragma unroll
    for (int tt = 0; tt < 4; ++tt) {
        int tl = ty * 4 + tt;
        int t = t0 + tl;
        float u = 0.f, v = 0.f;
        if (t < NFRAMES) {
            int j = j0 + tx;
            int base = t * HOP - PADW;
            int m1 = base + j + 1;
            int m2 = base + 2047 - j;     // FIXED: was base + 1023 - j (double-subtracted pad)
            m1 = m1 < 0 ? -m1 : (m1 >= LEN ? 2 * LEN - 2 - m1 : m1);
            m2 = m2 < 0 ? -m2 : (m2 >= LEN ? 2 * LEN - 2 - m2 : m2);
            float a  = xb[m1];
            float bb = xb[m2];
            u = a + bb;
            v = a - bb;
            if (j == 1023) { u = a; v = 0.f; }
        }
        su[tl][tx] = tf32r(u);
        sv[tl][tx] = tf32r(v);
    }
    __syncthreads();

    int t = t0 + tx;
    if (t >= NFRAMES) return;
    int bt = b * NFRAMES + t;
#pragma unroll
    for (int jj = 0; jj < 4; ++jj) {
        int jl = ty * 4 + jj;
        int j = j0 + jl;
        g_Ut[(size_t)j * NPAD + bt] = su[tx][jl];
        g_Vt[(size_t)j * NPAD + bt] = sv[tx][jl];
    }
}

// ---------------- kernel 3: TF32 mma.sync GEMM, cp.async double-buffered ----------------
// block tile 128(M) x 128(N), 8 warps (2x4), warp tile 64x32, k-step 16
#define MMA_TF32(d, a, b)                                                       \
    asm volatile(                                                               \
        "mma.sync.aligned.m16n8k8.row.col.f32.tf32.tf32.f32 "                   \
        "{%0,%1,%2,%3},{%4,%5,%6,%7},{%8,%9},{%0,%1,%2,%3};"                    \
        : "+f"(d[0]), "+f"(d[1]), "+f"(d[2]), "+f"(d[3])                        \
        : "r"(a[0]), "r"(a[1]), "r"(a[2]), "r"(a[3]), "r"(b[0]), "r"(b[1]))

__global__ void __launch_bounds__(256, 2) gemm_kernel(float* __restrict__ out) {
    const int z = blockIdx.z;
    const float* __restrict__ W = z ? g_Wst : g_Wct;
    const float* __restrict__ X = z ? g_Vt  : g_Ut;

    __shared__ float As[2][16 * SSTR];
    __shared__ float Bs[2][16 * SSTR];

    const int tid  = threadIdx.x;
    const int warp = tid >> 5, lane = tid & 31;
    const int wm = warp & 1;
    const int wn = warp >> 1;
    const int g  = lane >> 2;
    const int tg = lane & 3;
    const int m0 = blockIdx.y * 128;
    const int n0 = blockIdx.x * 128;

    const int r0c = tid >> 5, c0c = (tid & 31) * 4;           // rows 0..7
    const int r1c = r0c + 8;                                  // rows 8..15
    const float* A0 = W + (size_t)r0c * MPAD + m0 + c0c;
    const float* A1 = W + (size_t)r1c * MPAD + m0 + c0c;
    const float* B0 = X + (size_t)r0c * NPAD + n0 + c0c;
    const float* B1 = X + (size_t)r1c * NPAD + n0 + c0c;
    const uint32_t sA0 = (uint32_t)__cvta_generic_to_shared(&As[0][r0c * SSTR + c0c]);
    const uint32_t sA1 = (uint32_t)__cvta_generic_to_shared(&As[0][r1c * SSTR + c0c]);
    const uint32_t sB0 = (uint32_t)__cvta_generic_to_shared(&Bs[0][r0c * SSTR + c0c]);
    const uint32_t sB1 = (uint32_t)__cvta_generic_to_shared(&Bs[0][r1c * SSTR + c0c]);
    const uint32_t stgB = (uint32_t)(16 * SSTR * sizeof(float));

    auto issue = [&](int c) {
        size_t koff = (size_t)c * 16;
        uint32_t so = (c & 1) ? stgB : 0u;
        cpa16(sA0 + so, A0 + koff * MPAD);
        cpa16(sA1 + so, A1 + koff * MPAD);
        cpa16(sB0 + so, B0 + koff * NPAD);
        cpa16(sB1 + so, B1 + koff * NPAD);
        cpa_commit();
    };

    float acc[4][4][4];
#pragma unroll
    for (int i = 0; i < 4; ++i)
#pragma unroll
        for (int j = 0; j < 4; ++j)
#pragma unroll
            for (int c = 0; c < 4; ++c) acc[i][j][c] = 0.f;

    const int abase = wm * 64 + g;
    const int bbase = wn * 32 + g;

    issue(0);

    for (int c = 0; c < NKT; ++c) {
        // issue next stage first, then wait_group 1 -> group c guaranteed done
        if (c + 1 < NKT) { issue(c + 1); cpa_wait<1>(); }
        else             { cpa_wait<0>(); }
        __syncthreads();

        const uint32_t* Asu = (const uint32_t*)As[c & 1];
        const uint32_t* Bsu = (const uint32_t*)Bs[c & 1];
#pragma unroll
        for (int s = 0; s < 2; ++s) {
            const int krow = 8 * s + tg;
            uint32_t bf[4][2];
#pragma unroll
            for (int j = 0; j < 4; ++j) {
                bf[j][0] = Bsu[krow * SSTR + bbase + 8 * j];
                bf[j][1] = Bsu[(krow + 4) * SSTR + bbase + 8 * j];
            }
#pragma unroll
            for (int i = 0; i < 4; ++i) {
                uint32_t af[4];
                const int mcol = abase + 16 * i;
                af[0] = Asu[krow * SSTR + mcol];
                af[1] = Asu[krow * SSTR + mcol + 8];
                af[2] = Asu[(krow + 4) * SSTR + mcol];
                af[3] = Asu[(krow + 4) * SSTR + mcol + 8];
#pragma unroll
                for (int j = 0; j < 4; ++j) MMA_TF32(acc[i][j], af, bf[j]);
            }
        }
        __syncthreads();   // protects buffer c&1 from being overwritten by issue(c+2)
    }

    // epilogue: out[b][k][t][z], imag negated
    int btc[4][2], bc[4][2], tc[4][2];
#pragma unroll
    for (int j = 0; j < 4; ++j)
#pragma unroll
        for (int q = 0; q < 2; ++q) {
            int bt = n0 + wn * 32 + 8 * j + 2 * tg + q;
            btc[j][q] = bt;
            bc[j][q] = bt / NFRAMES;
            tc[j][q] = bt - bc[j][q] * NFRAMES;
        }
#pragma unroll
    for (int i = 0; i < 4; ++i) {
#pragma unroll
        for (int h = 0; h < 2; ++h) {
            int k = m0 + wm * 64 + 16 * i + g + 8 * h;
            if (k >= FREQ) continue;
#pragma unroll
            for (int j = 0; j < 4; ++j)
#pragma unroll
                for (int q = 0; q < 2; ++q) {
                    if (btc[j][q] >= NBT) continue;
                    float v = acc[i][j][2 * h + q];
                    if (z) v = -v;
                    out[((((size_t)bc[j][q] * FREQ + k) * NFRAMES + tc[j][q]) << 1) + z] = v;
                }
        }
    }
}

// ---------------- launch ----------------
extern "C" void kernel_launch(void* const* d_in, const int* in_sizes, int n_in,
                              void* d_out, int out_size) {
    const float* x    = (const float*)d_in[0];
    const float* wcos = (const float*)d_in[1];
    const float* wsin = (const float*)d_in[2];
    float* out = (float*)d_out;

    wprep_kernel<<<dim3((MPAD + 127) / 128, KDIM), 128>>>(wcos, wsin);
    frame_kernel<<<dim3((NFRAMES + 31) / 32, KDIM / 32, BATCH), 256>>>(x);
    gemm_kernel<<<dim3(NPAD / 128, MPAD / 128, 2), 256>>>(out);
}

// round 9
// speedup vs baseline: 3.5390x; 1.0516x over previous
#include <cuda_runtime.h>
#include <cstdint>

// ---------------- problem constants ----------------
#define BATCH     32
#define LEN       220500
#define HOP       512
#define PADW      1024
#define FREQ      1025
#define NFRAMES   431
#define NBT       (BATCH * NFRAMES)     // 13792
#define KDIM      1024                  // folded K
#define NPAD      13824                 // 108 * 128
#define MPAD      1152                  // 9 * 128
#define NFFT      2048
#define SSTR      136                   // smem row stride (floats) -> conflict-free frags
#define NKT       (KDIM / 16)           // 64 k-tiles
#define STAGES    5
#define STAGE_FLOATS (2 * 16 * SSTR)    // A+B per stage = 4352 floats (17408 B)
#define SMEM_BYTES (STAGES * STAGE_FLOATS * 4)   // 87040 B

// ---------------- device scratch ----------------
__device__ float g_Ut [KDIM * NPAD];
__device__ float g_Vt [KDIM * NPAD];
__device__ float g_Wct[KDIM * MPAD];
__device__ float g_Wst[KDIM * MPAD];

__device__ __forceinline__ float tf32r(float x) {
    uint32_t u; asm("cvt.rna.tf32.f32 %0, %1;" : "=r"(u) : "f"(x));
    return __uint_as_float(u);
}

__device__ __forceinline__ void cpa16(uint32_t s, const void* g) {
    asm volatile("cp.async.cg.shared.global [%0], [%1], 16;" :: "r"(s), "l"(g));
}
__device__ __forceinline__ void cpa_commit() {
    asm volatile("cp.async.commit_group;" ::: "memory");
}
template <int N>
__device__ __forceinline__ void cpa_wait() {
    asm volatile("cp.async.wait_group %0;" :: "n"(N) : "memory");
}

// ---------------- kernel 1: transpose + shift weights (tf32-rounded) ----------------
__global__ void wprep_kernel(const float* __restrict__ wcos,
                             const float* __restrict__ wsin) {
    int k = blockIdx.x * blockDim.x + threadIdx.x;
    int j = blockIdx.y;
    if (k >= MPAD) return;
    float c = 0.f, s = 0.f;
    if (k < FREQ) {
        c = tf32r(wcos[(size_t)k * NFFT + j + 1]);
        s = tf32r(wsin[(size_t)k * NFFT + j + 1]);
    }
    g_Wct[j * MPAD + k] = c;
    g_Wst[j * MPAD + k] = s;
}

// ---------------- kernel 2: fused reflect-pad + fold + transpose ----------------
// base = t*HOP - PADW
// U[j][bt] = x[refl(base + j + 1)] + x[refl(base + 2047 - j)]   (j==1023 -> center tap once)
// V[j][bt] = x[refl(base + j + 1)] - x[refl(base + 2047 - j)]
__global__ void __launch_bounds__(256) frame_kernel(const float* __restrict__ x) {
    __shared__ float su[32][33];
    __shared__ float sv[32][33];
    const int b  = blockIdx.z;
    const int t0 = blockIdx.x * 32;
    const int j0 = blockIdx.y * 32;
    const int tx = threadIdx.x & 31;
    const int ty = threadIdx.x >> 5;
    const float* __restrict__ xb = x + (size_t)b * LEN;

#pragma unroll
    for (int tt = 0; tt < 4; ++tt) {
        int tl = ty * 4 + tt;
        int t = t0 + tl;
        float u = 0.f, v = 0.f;
        if (t < NFRAMES) {
            int j = j0 + tx;
            int base = t * HOP - PADW;
            int m1 = base + j + 1;
            int m2 = base + 2047 - j;
            m1 = m1 < 0 ? -m1 : (m1 >= LEN ? 2 * LEN - 2 - m1 : m1);
            m2 = m2 < 0 ? -m2 : (m2 >= LEN ? 2 * LEN - 2 - m2 : m2);
            float a  = xb[m1];
            float bb = xb[m2];
            u = a + bb;
            v = a - bb;
            if (j == 1023) { u = a; v = 0.f; }
        }
        su[tl][tx] = tf32r(u);
        sv[tl][tx] = tf32r(v);
    }
    __syncthreads();

    int t = t0 + tx;
    if (t >= NFRAMES) return;
    int bt = b * NFRAMES + t;
#pragma unroll
    for (int jj = 0; jj < 4; ++jj) {
        int jl = ty * 4 + jj;
        int j = j0 + jl;
        g_Ut[(size_t)j * NPAD + bt] = su[tx][jl];
        g_Vt[(size_t)j * NPAD + bt] = sv[tx][jl];
    }
}

// ---------------- kernel 3: TF32 mma.sync GEMM, 5-stage cp.async ring ----------------
// block tile 128(M) x 128(N), 8 warps (2x4), warp tile 64x32, k-step 16
#define MMA_TF32(d, a, b)                                                       \
    asm volatile(                                                               \
        "mma.sync.aligned.m16n8k8.row.col.f32.tf32.tf32.f32 "                   \
        "{%0,%1,%2,%3},{%4,%5,%6,%7},{%8,%9},{%0,%1,%2,%3};"                    \
        : "+f"(d[0]), "+f"(d[1]), "+f"(d[2]), "+f"(d[3])                        \
        : "r"(a[0]), "r"(a[1]), "r"(a[2]), "r"(a[3]), "r"(b[0]), "r"(b[1]))

__global__ void __launch_bounds__(256, 2) gemm_kernel(float* __restrict__ out) {
    extern __shared__ float smem[];
    const int z = blockIdx.z;
    const float* __restrict__ W = z ? g_Wst : g_Wct;
    const float* __restrict__ X = z ? g_Vt  : g_Ut;

    const int tid  = threadIdx.x;
    const int warp = tid >> 5, lane = tid & 31;
    const int wm = warp & 1;
    const int wn = warp >> 1;
    const int g  = lane >> 2;
    const int tg = lane & 3;
    const int m0 = blockIdx.y * 128;
    const int n0 = blockIdx.x * 128;

    // cp.async assignment: thread covers rows r0c and r0c+8 of the 16-row chunk
    const int r0c = tid >> 5, c0c = (tid & 31) * 4;
    const int r1c = r0c + 8;
    const float* A0 = W + (size_t)r0c * MPAD + m0 + c0c;
    const float* A1 = W + (size_t)r1c * MPAD + m0 + c0c;
    const float* B0 = X + (size_t)r0c * NPAD + n0 + c0c;
    const float* B1 = X + (size_t)r1c * NPAD + n0 + c0c;

    const uint32_t sbase = (uint32_t)__cvta_generic_to_shared(smem);
    const uint32_t oA0 = (uint32_t)((r0c * SSTR + c0c) * 4);
    const uint32_t oA1 = (uint32_t)((r1c * SSTR + c0c) * 4);
    const uint32_t oB0 = oA0 + 16 * SSTR * 4;
    const uint32_t oB1 = oA1 + 16 * SSTR * 4;

    auto issue = [&](int c, int slot) {
        size_t koff = (size_t)c * 16;
        uint32_t sb = sbase + (uint32_t)(slot * STAGE_FLOATS * 4);
        cpa16(sb + oA0, A0 + koff * MPAD);
        cpa16(sb + oA1, A1 + koff * MPAD);
        cpa16(sb + oB0, B0 + koff * NPAD);
        cpa16(sb + oB1, B1 + koff * NPAD);
        cpa_commit();
    };

    float acc[4][4][4];
#pragma unroll
    for (int i = 0; i < 4; ++i)
#pragma unroll
        for (int j = 0; j < 4; ++j)
#pragma unroll
            for (int c = 0; c < 4; ++c) acc[i][j][c] = 0.f;

    const int abase = wm * 64 + g;
    const int bbase = wn * 32 + g;

    // prologue: fill STAGES-1 = 4 stages
#pragma unroll
    for (int p = 0; p < STAGES - 1; ++p) issue(p, p);

    int slot = 0;        // consume slot  (c % 5)
    int islot = 4;       // issue slot    ((c+4) % 5)
    for (int c = 0; c < NKT; ++c) {
        // guarantee group c complete (tail-correct wait counts)
        const int rem = NKT - 1 - c;
        if (rem >= 3)      cpa_wait<3>();
        else if (rem == 2) cpa_wait<2>();
        else if (rem == 1) cpa_wait<1>();
        else               cpa_wait<0>();
        __syncthreads();                       // all warps done with slot (c-1)%5
        if (c + STAGES - 1 < NKT) issue(c + STAGES - 1, islot);

        const uint32_t* Asu = (const uint32_t*)(smem + slot * STAGE_FLOATS);
        const uint32_t* Bsu = Asu + 16 * SSTR;
#pragma unroll
        for (int s = 0; s < 2; ++s) {
            const int krow = 8 * s + tg;
            uint32_t bf[4][2];
#pragma unroll
            for (int j = 0; j < 4; ++j) {
                bf[j][0] = Bsu[krow * SSTR + bbase + 8 * j];
                bf[j][1] = Bsu[(krow + 4) * SSTR + bbase + 8 * j];
            }
#pragma unroll
            for (int i = 0; i < 4; ++i) {
                uint32_t af[4];
                const int mcol = abase + 16 * i;
                af[0] = Asu[krow * SSTR + mcol];
                af[1] = Asu[krow * SSTR + mcol + 8];
                af[2] = Asu[(krow + 4) * SSTR + mcol];
                af[3] = Asu[(krow + 4) * SSTR + mcol + 8];
#pragma unroll
                for (int j = 0; j < 4; ++j) MMA_TF32(acc[i][j], af, bf[j]);
            }
        }
        slot  = (slot  == STAGES - 1) ? 0 : slot + 1;
        islot = (islot == STAGES - 1) ? 0 : islot + 1;
    }

    // epilogue: out[b][k][t][z], imag negated
    int btc[4][2], bc[4][2], tc[4][2];
#pragma unroll
    for (int j = 0; j < 4; ++j)
#pragma unroll
        for (int q = 0; q < 2; ++q) {
            int bt = n0 + wn * 32 + 8 * j + 2 * tg + q;
            btc[j][q] = bt;
            bc[j][q] = bt / NFRAMES;
            tc[j][q] = bt - bc[j][q] * NFRAMES;
        }
#pragma unroll
    for (int i = 0; i < 4; ++i) {
#pragma unroll
        for (int h = 0; h < 2; ++h) {
            int k = m0 + wm * 64 + 16 * i + g + 8 * h;
            if (k >= FREQ) continue;
#pragma unroll
            for (int j = 0; j < 4; ++j)
#pragma unroll
                for (int q = 0; q < 2; ++q) {
                    if (btc[j][q] >= NBT) continue;
                    float v = acc[i][j][2 * h + q];
                    if (z) v = -v;
                    out[((((size_t)bc[j][q] * FREQ + k) * NFRAMES + tc[j][q]) << 1) + z] = v;
                }
        }
    }
}

// ---------------- launch ----------------
extern "C" void kernel_launch(void* const* d_in, const int* in_sizes, int n_in,
                              void* d_out, int out_size) {
    const float* x    = (const float*)d_in[0];
    const float* wcos = (const float*)d_in[1];
    const float* wsin = (const float*)d_in[2];
    float* out = (float*)d_out;

    cudaFuncSetAttribute(gemm_kernel, cudaFuncAttributeMaxDynamicSharedMemorySize, SMEM_BYTES);

    wprep_kernel<<<dim3((MPAD + 127) / 128, KDIM), 128>>>(wcos, wsin);
    frame_kernel<<<dim3((NFRAMES + 31) / 32, KDIM / 32, BATCH), 256>>>(x);
    gemm_kernel<<<dim3(NPAD / 128, MPAD / 128, 2), 256, SMEM_BYTES>>>(out);
}